// round 11
// baseline (speedup 1.0000x reference)
#include <cuda_runtime.h>

#define NATOMS 100000
#define NPAIRS 2000000
#define FDIM 64
#define RDIM 16
#define LN2F 0.6931471805599453f

// Scratch (device globals: allocation-free per harness rules)
__device__ float g_yj[NATOMS * FDIM];   // softplus(x@Wj+bj) per atom
__device__ float g_acc[NATOMS * FDIM];  // x_i' accumulator; pairs red into it

__device__ __forceinline__ float sp(float x) {
    // softplus = max(x,0) + log1p(exp(-|x|))
    return fmaxf(x, 0.f) + log1pf(__expf(-fabsf(x)));
}

// ---------------------------------------------------------------------------
// Kernel 1: per-atom. x = sp(emb)-ln2; g_acc = sp(x@Wi+bi); g_yj = sp(x@Wj+bj)
// block = 256 threads = 4 atoms x 64 features
// ---------------------------------------------------------------------------
__global__ void node_kernel(const float* __restrict__ emb,
                            const float* __restrict__ Wi, const float* __restrict__ bi,
                            const float* __restrict__ Wj, const float* __restrict__ bj)
{
    __shared__ float Wis[FDIM * FDIM];
    __shared__ float Wjs[FDIM * FDIM];
    __shared__ float xs[4][68];   // padded: (a*68+k)%32 distinct across a

    const int tid = threadIdx.x;
    for (int i = tid; i < FDIM * FDIM; i += blockDim.x) {
        Wis[i] = Wi[i];
        Wjs[i] = Wj[i];
    }
    const int a = tid >> 6;      // 0..3
    const int c = tid & 63;      // 0..63
    const float bic = bi[c];
    const float bjc = bj[c];
    __syncthreads();

    const int ntiles = NATOMS / 4;
    for (int t = blockIdx.x; t < ntiles; t += gridDim.x) {
        const int atom = t * 4 + a;
        const float e = emb[(size_t)atom * FDIM + c];
        xs[a][c] = sp(e) - LN2F;
        __syncthreads();

        float ai = bic, aj = bjc;
        #pragma unroll
        for (int k = 0; k < FDIM; k++) {
            const float xv = xs[a][k];
            ai = fmaf(xv, Wis[k * FDIM + c], ai);
            aj = fmaf(xv, Wjs[k * FDIM + c], aj);
        }
        g_acc[(size_t)atom * FDIM + c] = sp(ai);
        g_yj [(size_t)atom * FDIM + c] = sp(aj);
        __syncthreads();   // before next tile overwrites xs
    }
}

// ---------------------------------------------------------------------------
// Kernel 2: per-pair. f' = f @ G^T ; msg = y_j[idx_j] * f' ; red into g_acc[idx_i]
// 16 threads per pair, each owns 4 features (float4). block = 256 = 16 pairs.
// ---------------------------------------------------------------------------
__global__ void pair_kernel(const int* __restrict__ pidx,
                            const float* __restrict__ fij,
                            const float* __restrict__ G)
{
    __shared__ float Gt[RDIM * FDIM];   // Gt[r*64+c] = G[c*16+r]  (transposed)
    for (int i = threadIdx.x; i < RDIM * FDIM; i += blockDim.x) {
        const int r = i >> 6, c = i & 63;
        Gt[i] = G[c * RDIM + r];
    }
    __syncthreads();

    const int q = threadIdx.x & 15;          // feature group 0..15
    const int lanebase = threadIdx.x & 16;   // shfl source base within warp
    const int ppb = blockDim.x >> 4;         // pairs per block per iter

    for (int p = blockIdx.x * ppb + (threadIdx.x >> 4); p < NPAIRS;
         p += gridDim.x * ppb) {
        const float fv = fij[(size_t)p * RDIM + q];   // coalesced 128B/warp
        const int ii = pidx[p];
        const int jj = pidx[NPAIRS + p];

        float4 acc = make_float4(0.f, 0.f, 0.f, 0.f);
        #pragma unroll
        for (int r = 0; r < RDIM; r++) {
            const float fr = __shfl_sync(0xffffffffu, fv, lanebase + r);
            const float4 g = *reinterpret_cast<const float4*>(Gt + r * FDIM + q * 4);
            acc.x = fmaf(fr, g.x, acc.x);
            acc.y = fmaf(fr, g.y, acc.y);
            acc.z = fmaf(fr, g.z, acc.z);
            acc.w = fmaf(fr, g.w, acc.w);
        }

        const float4 y =
            *reinterpret_cast<const float4*>(g_yj + (size_t)jj * FDIM + q * 4);
        const float mx = acc.x * y.x;
        const float my = acc.y * y.y;
        const float mz = acc.z * y.z;
        const float mw = acc.w * y.w;

        float* dst = g_acc + (size_t)ii * FDIM + q * 4;  // 16B aligned
        asm volatile("red.global.add.v4.f32 [%0], {%1,%2,%3,%4};"
                     :: "l"(dst), "f"(mx), "f"(my), "f"(mz), "f"(mw)
                     : "memory");
    }
}

// ---------------------------------------------------------------------------
// Kernel 3: per-atom epilogue. v = g_acc row; 3 residual blocks; out = sp(v)@Wv+bv
// block = 512 threads = 32 atoms x 16 feature-groups (float4 per thread).
// All 7 weight matrices + biases in dynamic SMEM.
// ---------------------------------------------------------------------------
#define EPI_ATOMS 32
#define VPAD 72   // padded row stride (floats); 72*4 = 288B, 16B-aligned, bank-safe

__global__ void epi_kernel(const float* __restrict__ rW1, const float* __restrict__ rb1,
                           const float* __restrict__ rW2, const float* __restrict__ rb2,
                           const float* __restrict__ Wv,  const float* __restrict__ bv,
                           float* __restrict__ out)
{
    extern __shared__ float sm[];
    float* Wsh = sm;                            // 7*4096: [W1_0..2][W2_0..2][Wv]
    float* vs  = Wsh + 7 * 4096;                // 32*72
    float* hs  = vs  + EPI_ATOMS * VPAD;        // 32*72
    float* b1s = hs  + EPI_ATOMS * VPAD;        // 192
    float* b2s = b1s + 192;                     // 192
    float* bvs = b2s + 192;                     // 64

    const int tid = threadIdx.x;
    for (int i = tid; i < 3 * 4096; i += blockDim.x) {
        Wsh[i] = rW1[i];
        Wsh[3 * 4096 + i] = rW2[i];
    }
    for (int i = tid; i < 4096; i += blockDim.x) Wsh[6 * 4096 + i] = Wv[i];
    for (int i = tid; i < 192;  i += blockDim.x) { b1s[i] = rb1[i]; b2s[i] = rb2[i]; }
    for (int i = tid; i < 64;   i += blockDim.x) bvs[i] = bv[i];
    __syncthreads();

    const int a = tid >> 4;    // 0..31
    const int q = tid & 15;    // 0..15
    float* vrow = vs + a * VPAD;
    float* hrow = hs + a * VPAD;

    const int ntiles = NATOMS / EPI_ATOMS;
    for (int t = blockIdx.x; t < ntiles; t += gridDim.x) {
        const int atom = t * EPI_ATOMS + a;
        float4 v = *reinterpret_cast<const float4*>(g_acc + (size_t)atom * FDIM + q * 4);
        reinterpret_cast<float4*>(vrow)[q] = v;
        __syncthreads();

        #pragma unroll
        for (int l = 0; l < 3; l++) {
            // h = sp(v @ W1_l + b1_l)
            const float* W1 = Wsh + l * 4096;
            float4 h = make_float4(b1s[l * 64 + q * 4 + 0], b1s[l * 64 + q * 4 + 1],
                                   b1s[l * 64 + q * 4 + 2], b1s[l * 64 + q * 4 + 3]);
            #pragma unroll
            for (int k = 0; k < FDIM; k++) {
                const float svv = vrow[k];
                const float4 w = *reinterpret_cast<const float4*>(W1 + k * 64 + q * 4);
                h.x = fmaf(svv, w.x, h.x);
                h.y = fmaf(svv, w.y, h.y);
                h.z = fmaf(svv, w.z, h.z);
                h.w = fmaf(svv, w.w, h.w);
            }
            h.x = sp(h.x); h.y = sp(h.y); h.z = sp(h.z); h.w = sp(h.w);
            reinterpret_cast<float4*>(hrow)[q] = h;
            __syncthreads();

            // v += h @ W2_l + b2_l
            const float* W2 = Wsh + (3 + l) * 4096;
            float4 d = make_float4(b2s[l * 64 + q * 4 + 0], b2s[l * 64 + q * 4 + 1],
                                   b2s[l * 64 + q * 4 + 2], b2s[l * 64 + q * 4 + 3]);
            #pragma unroll
            for (int k = 0; k < FDIM; k++) {
                const float hv = hrow[k];
                const float4 w = *reinterpret_cast<const float4*>(W2 + k * 64 + q * 4);
                d.x = fmaf(hv, w.x, d.x);
                d.y = fmaf(hv, w.y, d.y);
                d.z = fmaf(hv, w.z, d.z);
                d.w = fmaf(hv, w.w, d.w);
            }
            v.x += d.x; v.y += d.y; v.z += d.z; v.w += d.w;
            reinterpret_cast<float4*>(vrow)[q] = v;
            __syncthreads();
        }

        // out = sp(v) @ Wv + bv
        float4 s = make_float4(sp(v.x), sp(v.y), sp(v.z), sp(v.w));
        reinterpret_cast<float4*>(hrow)[q] = s;
        __syncthreads();

        const float* Wl = Wsh + 6 * 4096;
        float4 o = make_float4(bvs[q * 4 + 0], bvs[q * 4 + 1],
                               bvs[q * 4 + 2], bvs[q * 4 + 3]);
        #pragma unroll
        for (int k = 0; k < FDIM; k++) {
            const float svv = hrow[k];
            const float4 w = *reinterpret_cast<const float4*>(Wl + k * 64 + q * 4);
            o.x = fmaf(svv, w.x, o.x);
            o.y = fmaf(svv, w.y, o.y);
            o.z = fmaf(svv, w.z, o.z);
            o.w = fmaf(svv, w.w, o.w);
        }
        *reinterpret_cast<float4*>(out + (size_t)atom * FDIM + q * 4) = o;
        __syncthreads();   // before next tile reuses vrow/hrow
    }
}

// ---------------------------------------------------------------------------
extern "C" void kernel_launch(void* const* d_in, const int* in_sizes, int n_in,
                              void* d_out, int out_size)
{
    const int*   pidx = (const int*)  d_in[0];   // pair_indices [2, P]
    const float* fij  = (const float*)d_in[1];   // f_ij [P,1,R]
    // d_in[2] = d_ij (unused by the reference math)
    const float* emb  = (const float*)d_in[3];   // atomic_embedding [N,F]
    const float* G    = (const float*)d_in[4];   // [F,R]
    const float* Wi   = (const float*)d_in[5];
    const float* bi   = (const float*)d_in[6];
    const float* Wj   = (const float*)d_in[7];
    const float* bj   = (const float*)d_in[8];
    const float* rW1  = (const float*)d_in[9];   // [3,F,F]
    const float* rb1  = (const float*)d_in[10];
    const float* rW2  = (const float*)d_in[11];
    const float* rb2  = (const float*)d_in[12];
    const float* Wv   = (const float*)d_in[13];
    const float* bv   = (const float*)d_in[14];
    float* out = (float*)d_out;

    // Kernel 1: node transforms (also initializes g_acc with x_i')
    node_kernel<<<1184, 256>>>(emb, Wi, bi, Wj, bj);

    // Kernel 2: pair messages + segment-sum via vector reductions.
    // grid chosen so 2,000,000 % (1250 blocks * 16 pairs) == 0 -> uniform warps.
    pair_kernel<<<1250, 256>>>(pidx, fij, G);

    // Kernel 3: residual MLP chain + output projection
    const int epi_smem = (7 * 4096 + 2 * EPI_ATOMS * VPAD + 192 + 192 + 64) * 4;
    cudaFuncSetAttribute(epi_kernel, cudaFuncAttributeMaxDynamicSharedMemorySize,
                         epi_smem);
    epi_kernel<<<296, 512, epi_smem>>>(rW1, rb1, rW2, rb2, Wv, bv, out);
}

// round 12
// speedup vs baseline: 1.4014x; 1.4014x over previous
#include <cuda_runtime.h>

#define NATOMS 100000
#define NPAIRS 2000000
#define FDIM 64
#define RDIM 16
#define LN2F 0.6931471805599453f

typedef unsigned long long u64;

// Scratch (device globals: allocation-free per harness rules)
__device__ float g_yj[NATOMS * FDIM];   // softplus(x@Wj+bj) per atom
__device__ float g_acc[NATOMS * FDIM];  // x_i' accumulator; pairs red into it

__device__ __forceinline__ float sp(float x) {
    return fmaxf(x, 0.f) + log1pf(__expf(-fabsf(x)));
}

// ---- packed f32x2 helpers (Blackwell FFMA2: 2 fp32 lanes per issue) ----
__device__ __forceinline__ u64 fma2(u64 a, u64 b, u64 c) {
    u64 d;
    asm("fma.rn.f32x2 %0, %1, %2, %3;" : "=l"(d) : "l"(a), "l"(b), "l"(c));
    return d;
}
__device__ __forceinline__ u64 mul2(u64 a, u64 b) {
    u64 d;
    asm("mul.rn.f32x2 %0, %1, %2;" : "=l"(d) : "l"(a), "l"(b));
    return d;
}
__device__ __forceinline__ u64 splat2(float v) {
    u64 r;
    asm("mov.b64 %0, {%1, %1};" : "=l"(r) : "f"(v));
    return r;
}
__device__ __forceinline__ u64 pack2(float lo, float hi) {
    u64 r;
    asm("mov.b64 %0, {%1, %2};" : "=l"(r) : "f"(lo), "f"(hi));
    return r;
}
__device__ __forceinline__ float2 unpack2(u64 v) {
    float lo, hi;
    asm("mov.b64 {%0, %1}, %2;" : "=f"(lo), "=f"(hi) : "l"(v));
    return make_float2(lo, hi);
}

// ---------------------------------------------------------------------------
// Kernel 1: per-atom.  x = sp(emb)-ln2;  g_acc = sp(x@Wi+bi);  g_yj = sp(x@Wj+bj)
// Treated as one GEMM with N=128 (Wi|Wj concatenated).
// 512 threads: ag = tid>>5 (16 atom-groups x 4 atoms), qp = tid&31 (128 cols / 4).
// Each thread: 4 atoms x 4 cols, f32x2 accumulators.
// ---------------------------------------------------------------------------
#define NODE_TILE 64
#define XPAD 68

__global__ void __launch_bounds__(512, 2) node_kernel(
    const float* __restrict__ emb,
    const float* __restrict__ Wi, const float* __restrict__ bi,
    const float* __restrict__ Wj, const float* __restrict__ bj)
{
    __shared__ float Wc[FDIM * 128];   // row k: [Wi[k][0..63] | Wj[k][0..63]]
    __shared__ float bc[128];
    __shared__ float xs[NODE_TILE * XPAD];

    const int tid = threadIdx.x;
    for (int i = tid; i < FDIM * FDIM; i += 512) {
        const int k = i >> 6, c = i & 63;
        Wc[k * 128 + c]      = Wi[i];
        Wc[k * 128 + 64 + c] = Wj[i];
    }
    if (tid < 64) { bc[tid] = bi[tid]; bc[64 + tid] = bj[tid]; }
    __syncthreads();

    const int qp = tid & 31;   // output column group (4 cols of 128)
    const int ag = tid >> 5;   // atom group (4 atoms)
    const u64 bias0 = pack2(bc[qp * 4 + 0], bc[qp * 4 + 1]);
    const u64 bias1 = pack2(bc[qp * 4 + 2], bc[qp * 4 + 3]);

    const int ntiles = (NATOMS + NODE_TILE - 1) / NODE_TILE;
    for (int t = blockIdx.x; t < ntiles; t += gridDim.x) {
        // stage x = sp(emb) - ln2 for 64 atoms
        for (int i = tid; i < NODE_TILE * 16; i += 512) {
            const int a = i >> 4, qq = i & 15;
            const int atom = t * NODE_TILE + a;
            if (atom < NATOMS) {
                const float4 e = *reinterpret_cast<const float4*>(
                    emb + (size_t)atom * FDIM + qq * 4);
                float4 x;
                x.x = sp(e.x) - LN2F; x.y = sp(e.y) - LN2F;
                x.z = sp(e.z) - LN2F; x.w = sp(e.w) - LN2F;
                *reinterpret_cast<float4*>(xs + a * XPAD + qq * 4) = x;
            }
        }
        __syncthreads();

        u64 acc[4][2];
        #pragma unroll
        for (int i = 0; i < 4; i++) { acc[i][0] = bias0; acc[i][1] = bias1; }

        #pragma unroll 4
        for (int k0 = 0; k0 < FDIM; k0 += 4) {
            ulonglong2 w[4];
            #pragma unroll
            for (int j = 0; j < 4; j++)
                w[j] = *reinterpret_cast<const ulonglong2*>(
                    Wc + (k0 + j) * 128 + qp * 4);
            #pragma unroll
            for (int i = 0; i < 4; i++) {
                const float4 v = *reinterpret_cast<const float4*>(
                    xs + (ag * 4 + i) * XPAD + k0);
                acc[i][0] = fma2(splat2(v.x), w[0].x, acc[i][0]);
                acc[i][1] = fma2(splat2(v.x), w[0].y, acc[i][1]);
                acc[i][0] = fma2(splat2(v.y), w[1].x, acc[i][0]);
                acc[i][1] = fma2(splat2(v.y), w[1].y, acc[i][1]);
                acc[i][0] = fma2(splat2(v.z), w[2].x, acc[i][0]);
                acc[i][1] = fma2(splat2(v.z), w[2].y, acc[i][1]);
                acc[i][0] = fma2(splat2(v.w), w[3].x, acc[i][0]);
                acc[i][1] = fma2(splat2(v.w), w[3].y, acc[i][1]);
            }
        }

        float* const dstbase = (qp < 16) ? g_acc : g_yj;
        const int col = (qp & 15) * 4;
        #pragma unroll
        for (int i = 0; i < 4; i++) {
            const int atom = t * NODE_TILE + ag * 4 + i;
            if (atom < NATOMS) {
                const float2 p0 = unpack2(acc[i][0]);
                const float2 p1 = unpack2(acc[i][1]);
                const float4 o = make_float4(sp(p0.x), sp(p0.y), sp(p1.x), sp(p1.y));
                *reinterpret_cast<float4*>(dstbase + (size_t)atom * FDIM + col) = o;
            }
        }
        __syncthreads();   // before next tile overwrites xs
    }
}

// ---------------------------------------------------------------------------
// Kernel 2: per-pair. f' = f @ G^T ; msg = y_j[idx_j] * f' ; red into g_acc[idx_i]
// 16 threads/pair (q = 4 features each). f row loaded broadcast via __ldg
// (replaces 16 SHFLs); matmul in f32x2.
// ---------------------------------------------------------------------------
__global__ void __launch_bounds__(256) pair_kernel(
    const int* __restrict__ pidx,
    const float* __restrict__ fij,
    const float* __restrict__ G)
{
    __shared__ float Gt[RDIM * FDIM];   // Gt[r*64+c] = G[c*16+r]
    for (int i = threadIdx.x; i < RDIM * FDIM; i += blockDim.x) {
        const int r = i >> 6, c = i & 63;
        Gt[i] = G[c * RDIM + r];
    }
    __syncthreads();

    const int q = threadIdx.x & 15;
    const int ppb = 16;   // pairs per block per iter

    for (int p = blockIdx.x * ppb + (threadIdx.x >> 4); p < NPAIRS;
         p += gridDim.x * ppb) {
        const float* frow = fij + (size_t)p * RDIM;
        const float4 f0 = __ldg(reinterpret_cast<const float4*>(frow));
        const float4 f1 = __ldg(reinterpret_cast<const float4*>(frow + 4));
        const float4 f2 = __ldg(reinterpret_cast<const float4*>(frow + 8));
        const float4 f3 = __ldg(reinterpret_cast<const float4*>(frow + 12));
        const int ii = __ldg(pidx + p);
        const int jj = __ldg(pidx + NPAIRS + p);

        const float fv[16] = {f0.x, f0.y, f0.z, f0.w, f1.x, f1.y, f1.z, f1.w,
                              f2.x, f2.y, f2.z, f2.w, f3.x, f3.y, f3.z, f3.w};
        u64 a0 = 0ull, a1 = 0ull;
        #pragma unroll
        for (int r = 0; r < RDIM; r++) {
            const ulonglong2 g = *reinterpret_cast<const ulonglong2*>(
                Gt + r * FDIM + q * 4);
            const u64 s = splat2(fv[r]);
            a0 = fma2(s, g.x, a0);
            a1 = fma2(s, g.y, a1);
        }

        const float4 y = __ldg(reinterpret_cast<const float4*>(
            g_yj + (size_t)jj * FDIM + q * 4));
        const float2 m0 = unpack2(mul2(a0, pack2(y.x, y.y)));
        const float2 m1 = unpack2(mul2(a1, pack2(y.z, y.w)));

        float* dst = g_acc + (size_t)ii * FDIM + q * 4;  // 16B aligned
        asm volatile("red.global.add.v4.f32 [%0], {%1,%2,%3,%4};"
                     :: "l"(dst), "f"(m0.x), "f"(m0.y), "f"(m1.x), "f"(m1.y)
                     : "memory");
    }
}

// ---------------------------------------------------------------------------
// Kernel 3: epilogue. 7 chained 64x64 matmuls per atom, 4-atom register
// blocking + f32x2. 512 threads = 32 atom-groups x 16 col-groups; 128 atoms/tile.
// ---------------------------------------------------------------------------
#define EPI_TILE 128
#define VPAD 68   // 4*VPAD mod 32 = 16 -> conflict-free; 16B-aligned rows

__device__ __forceinline__ void gemm_tile(const float* __restrict__ W,
                                          const float* __restrict__ rows,
                                          int ag, int q,
                                          const float* __restrict__ bias,
                                          float4 o[4])
{
    const u64 b0 = pack2(bias[q * 4 + 0], bias[q * 4 + 1]);
    const u64 b1 = pack2(bias[q * 4 + 2], bias[q * 4 + 3]);
    u64 acc[4][2];
    #pragma unroll
    for (int i = 0; i < 4; i++) { acc[i][0] = b0; acc[i][1] = b1; }

    #pragma unroll 4
    for (int k0 = 0; k0 < FDIM; k0 += 4) {
        ulonglong2 w[4];
        #pragma unroll
        for (int j = 0; j < 4; j++)
            w[j] = *reinterpret_cast<const ulonglong2*>(W + (k0 + j) * 64 + q * 4);
        #pragma unroll
        for (int i = 0; i < 4; i++) {
            const float4 v = *reinterpret_cast<const float4*>(
                rows + (ag * 4 + i) * VPAD + k0);
            acc[i][0] = fma2(splat2(v.x), w[0].x, acc[i][0]);
            acc[i][1] = fma2(splat2(v.x), w[0].y, acc[i][1]);
            acc[i][0] = fma2(splat2(v.y), w[1].x, acc[i][0]);
            acc[i][1] = fma2(splat2(v.y), w[1].y, acc[i][1]);
            acc[i][0] = fma2(splat2(v.z), w[2].x, acc[i][0]);
            acc[i][1] = fma2(splat2(v.z), w[2].y, acc[i][1]);
            acc[i][0] = fma2(splat2(v.w), w[3].x, acc[i][0]);
            acc[i][1] = fma2(splat2(v.w), w[3].y, acc[i][1]);
        }
    }
    #pragma unroll
    for (int i = 0; i < 4; i++) {
        const float2 p0 = unpack2(acc[i][0]);
        const float2 p1 = unpack2(acc[i][1]);
        o[i] = make_float4(p0.x, p0.y, p1.x, p1.y);
    }
}

__global__ void __launch_bounds__(512) epi_kernel(
    const float* __restrict__ rW1, const float* __restrict__ rb1,
    const float* __restrict__ rW2, const float* __restrict__ rb2,
    const float* __restrict__ Wv,  const float* __restrict__ bv,
    float* __restrict__ out)
{
    extern __shared__ float sm[];
    float* Wsh = sm;                        // 7*4096: [W1_0..2][W2_0..2][Wv]
    float* vs  = Wsh + 7 * 4096;            // 128*68
    float* hs  = vs  + EPI_TILE * VPAD;     // 128*68
    float* b1s = hs  + EPI_TILE * VPAD;     // 192
    float* b2s = b1s + 192;                 // 192
    float* bvs = b2s + 192;                 // 64

    const int tid = threadIdx.x;
    for (int i = tid; i < 3 * 4096; i += 512) {
        Wsh[i] = rW1[i];
        Wsh[3 * 4096 + i] = rW2[i];
    }
    for (int i = tid; i < 4096; i += 512) Wsh[6 * 4096 + i] = Wv[i];
    if (tid < 192) { b1s[tid] = rb1[tid]; b2s[tid] = rb2[tid]; }
    if (tid < 64) bvs[tid] = bv[tid];
    __syncthreads();

    const int q  = tid & 15;
    const int ag = tid >> 4;   // 0..31

    const int ntiles = (NATOMS + EPI_TILE - 1) / EPI_TILE;
    for (int t = blockIdx.x; t < ntiles; t += gridDim.x) {
        const int abase = t * EPI_TILE + ag * 4;

        float4 v[4];
        #pragma unroll
        for (int i = 0; i < 4; i++) {
            const int atom = abase + i;
            v[i] = (atom < NATOMS)
                 ? *reinterpret_cast<const float4*>(g_acc + (size_t)atom * FDIM + q * 4)
                 : make_float4(0.f, 0.f, 0.f, 0.f);
            *reinterpret_cast<float4*>(vs + (ag * 4 + i) * VPAD + q * 4) = v[i];
        }
        __syncthreads();

        #pragma unroll 1
        for (int l = 0; l < 3; l++) {
            // h = sp(v @ W1_l + b1_l)
            float4 h[4];
            gemm_tile(Wsh + l * 4096, vs, ag, q, b1s + l * 64, h);
            #pragma unroll
            for (int i = 0; i < 4; i++) {
                h[i].x = sp(h[i].x); h[i].y = sp(h[i].y);
                h[i].z = sp(h[i].z); h[i].w = sp(h[i].w);
                *reinterpret_cast<float4*>(hs + (ag * 4 + i) * VPAD + q * 4) = h[i];
            }
            __syncthreads();

            // v += h @ W2_l + b2_l
            float4 d[4];
            gemm_tile(Wsh + (3 + l) * 4096, hs, ag, q, b2s + l * 64, d);
            #pragma unroll
            for (int i = 0; i < 4; i++) {
                v[i].x += d[i].x; v[i].y += d[i].y;
                v[i].z += d[i].z; v[i].w += d[i].w;
                *reinterpret_cast<float4*>(vs + (ag * 4 + i) * VPAD + q * 4) = v[i];
            }
            __syncthreads();
        }

        // out = sp(v) @ Wv + bv
        #pragma unroll
        for (int i = 0; i < 4; i++) {
            const float4 s = make_float4(sp(v[i].x), sp(v[i].y), sp(v[i].z), sp(v[i].w));
            *reinterpret_cast<float4*>(hs + (ag * 4 + i) * VPAD + q * 4) = s;
        }
        __syncthreads();

        float4 o[4];
        gemm_tile(Wsh + 6 * 4096, hs, ag, q, bvs, o);
        #pragma unroll
        for (int i = 0; i < 4; i++) {
            const int atom = abase + i;
            if (atom < NATOMS)
                *reinterpret_cast<float4*>(out + (size_t)atom * FDIM + q * 4) = o[i];
        }
        __syncthreads();   // before next tile overwrites vs/hs
    }
}

// ---------------------------------------------------------------------------
extern "C" void kernel_launch(void* const* d_in, const int* in_sizes, int n_in,
                              void* d_out, int out_size)
{
    const int*   pidx = (const int*)  d_in[0];   // pair_indices [2, P]
    const float* fij  = (const float*)d_in[1];   // f_ij [P,1,R]
    // d_in[2] = d_ij (unused by the reference math)
    const float* emb  = (const float*)d_in[3];   // atomic_embedding [N,F]
    const float* G    = (const float*)d_in[4];   // [F,R]
    const float* Wi   = (const float*)d_in[5];
    const float* bi   = (const float*)d_in[6];
    const float* Wj   = (const float*)d_in[7];
    const float* bj   = (const float*)d_in[8];
    const float* rW1  = (const float*)d_in[9];   // [3,F,F]
    const float* rb1  = (const float*)d_in[10];
    const float* rW2  = (const float*)d_in[11];
    const float* rb2  = (const float*)d_in[12];
    const float* Wv   = (const float*)d_in[13];
    const float* bv   = (const float*)d_in[14];
    float* out = (float*)d_out;

    // Kernel 1: node transforms (initializes g_acc with x_i', g_yj with x_j')
    node_kernel<<<296, 512>>>(emb, Wi, bi, Wj, bj);

    // Kernel 2: pair messages + segment-sum via vector reductions
    pair_kernel<<<1250, 256>>>(pidx, fij, G);

    // Kernel 3: residual MLP chain + output projection
    const int epi_smem = (7 * 4096 + 2 * EPI_TILE * VPAD + 192 + 192 + 64) * 4;
    cudaFuncSetAttribute(epi_kernel, cudaFuncAttributeMaxDynamicSharedMemorySize,
                         epi_smem);
    epi_kernel<<<148, 512, epi_smem>>>(rW1, rb1, rW2, rb2, Wv, bv, out);
}